// round 16
// baseline (speedup 1.0000x reference)
#include <cuda_runtime.h>

#define WIDTH  2048
#define HEIGHT 2048
#define HW (2048 * 2048)
#define KS  97
#define RAD 48

typedef unsigned long long ull;

// ---------------- device scratch (no allocations allowed) ----------------
__device__ float2 g_tmp[HW];   // vertically blurred field, interleaved (ch0, ch1)

// ---------------- packed fp32x2 ops, u64-native ----------------
__device__ __forceinline__ ull packf2(float lo, float hi) {
    ull u;
    asm("mov.b64 %0, {%1, %2};" : "=l"(u) : "f"(lo), "f"(hi));
    return u;
}
__device__ __forceinline__ void unpackf2(ull u, float& lo, float& hi) {
    asm("mov.b64 {%0, %1}, %2;" : "=f"(lo), "=f"(hi) : "l"(u));
}
__device__ __forceinline__ ull ffma2u(ull a, ull b, ull c) {
    ull d;
    asm("fma.rn.f32x2 %0, %1, %2, %3;" : "=l"(d) : "l"(a), "l"(b), "l"(c));
    return d;
}

// ---------------- inline weight table build (per-block, deterministic) ------
__device__ __forceinline__ void build_weights(
    ull* sw, const float* __restrict__ log_sigma, const float* __restrict__ log_alpha,
    bool mul_alpha, float* e0s, float* e1s, float* sums) {
    int t = threadIdx.x;
    float s0 = expf(log_sigma[0]);
    float s1 = expf(log_sigma[1]);
    if (t < KS) {
        float x = (float)(t - KS / 2);
        e0s[t] = expf(-x * x / (2.0f * s0 * s0));
        e1s[t] = expf(-x * x / (2.0f * s1 * s1));
    }
    __syncthreads();
    if (t == 0) {
        float a = 0.f, b = 0.f;
        for (int i = 0; i < KS; i++) { a += e0s[i]; b += e1s[i]; }
        sums[0] = a; sums[1] = b;
    }
    __syncthreads();
    if (t < KS) {
        float w0 = e0s[t] / sums[0];
        float w1 = e1s[t] / sums[1];
        if (mul_alpha) {
            w0 *= expf(log_alpha[0]);
            w1 *= expf(log_alpha[1]);
        }
        sw[t] = packf2(w0, w1);
    }
    __syncthreads();
}

// ================= K1: vertical blur, smem-staged column tile =================
// Block = 256 threads = 32 cols x 8 row-groups; output tile 32 cols x 64 rows.
// Input window (160 rows x 32 cols, as 2d-1) staged ONCE into transposed smem
// (stride 163 u64 -> conflict-free), killing L2 read redundancy.
// Conv: R=8, 16-slot register window.
#define VR    8
#define VROWS 64
#define VIN   160              // VROWS + 2*RAD
#define VSTR  163              // smem row stride per column (u64)

__global__ void __launch_bounds__(256, 3) vblur_kernel(
    const float* __restrict__ drand,
    const float* __restrict__ log_sigma, const float* __restrict__ log_alpha) {
    __shared__ ull sw[KS];
    __shared__ float e0s[KS], e1s[KS], sums[2];
    __shared__ ull tile[32 * VSTR];
    build_weights(sw, log_sigma, log_alpha, false, e0s, e1s, sums);

    int tid = threadIdx.x;
    int gx0 = blockIdx.x * 32;
    int y0  = blockIdx.y * VROWS;

    const float* d0 = drand;
    const float* d1 = drand + HW;
    const ull c_two  = packf2(2.f, 2.f);
    const ull c_mone = packf2(-1.f, -1.f);

    // stage input window: gmem coalesced reads, transposed conflict-free STS
#pragma unroll
    for (int it = 0; it < VIN * 32 / 256; it++) {
        int i   = it * 256 + tid;
        int row = i >> 5;              // 0..159
        int col = i & 31;
        int iy  = y0 - RAD + row;
        ull v = 0ull;
        if ((unsigned)iy < (unsigned)HEIGHT) {
            size_t off = (size_t)iy * WIDTH + gx0 + col;
            v = ffma2u(c_two, packf2(__ldg(d0 + off), __ldg(d1 + off)), c_mone);
        }
        tile[col * VSTR + row] = v;
    }
    __syncthreads();

    int c = tid & 31;
    int g = tid >> 5;                  // row-group: outputs y0+g*8 .. +7
    const ull* T = tile + c * VSTR + g * VR;   // T[m] = input (y0-48+g*8+m, col)

    ull acc[VR];
#pragma unroll
    for (int r = 0; r < VR; r++) acc[r] = 0ull;

    ull win[16];
#pragma unroll
    for (int k = 0; k < 16; k++) win[k] = T[k];

#pragma unroll
    for (int J = 0; J < 96; J += 8) {
#pragma unroll
        for (int jj = 0; jj < 8; jj++) {
            const int j = J + jj;
            ull wj = sw[j];
#pragma unroll
            for (int r = 0; r < VR; r++)
                acc[r] = ffma2u(wj, win[(j + r) & 15], acc[r]);
            if (J < 88) win[j & 15] = T[j + 16];
        }
    }
    {
        ull w96 = sw[96];
#pragma unroll
        for (int r = 0; r < VR; r++)
            acc[r] = ffma2u(w96, win[(96 + r) & 15], acc[r]);
    }

#pragma unroll
    for (int r = 0; r < VR; r++)
        ((ull*)g_tmp)[(size_t)(y0 + g * VR + r) * WIDTH + gx0 + c] = acc[r];
}

// ============ K2: horizontal blur + bilinear sample, warp-private ============
// 256 threads / 8 warps; warps 0-3 own row y0 (512-px segments), warps 4-7 row
// y0+1. R=16 per lane: x0 = lane*16 makes the skewed smem addressing AFFINE
// (sk(x0+m) = lane*17 + m + (m>>4)) -> window LDS are immediate-offset.
// __launch_bounds__(256,3) caps regs (~84) -> 3 blocks/SM (occ 23% -> 34%).
__device__ __forceinline__ int sk(int p) { return p + (p >> 4); }
#define HR      16
#define SEG_PX  512
#define SEG_LD  608                  // inputs 0..607 (max lane: 31*16+111)
#define SEGU    648                  // sk(607)=644 < 648 (u64 slots)

__global__ void __launch_bounds__(256, 3) hblur_sample_kernel(
    const float* __restrict__ img, const float* __restrict__ msk,
    float* __restrict__ out,
    const float* __restrict__ log_sigma, const float* __restrict__ log_alpha) {
    __shared__ ull sw[KS];
    __shared__ float e0s[KS], e1s[KS], sums[2];
    __shared__ ull sseg[8][SEGU];
    build_weights(sw, log_sigma, log_alpha, true, e0s, e1s, sums);

    int tid  = threadIdx.x;
    int lane = tid & 31;
    int wid  = tid >> 5;
    int y    = blockIdx.x * 2 + (wid >> 2);
    int segx = (wid & 3) * SEG_PX;                  // global x of segment start
    ull* S = sseg[wid];
    const ull* trow = ((const ull*)g_tmp) + (size_t)y * WIDTH;

    // Phase 1 (per-warp): load segment + halo, zero outside row
#pragma unroll
    for (int i = 0; i < SEG_LD / 32; i++) {
        int p  = i * 32 + lane;
        int gx = segx + p - RAD;
        ull v = 0ull;
        if ((unsigned)gx < (unsigned)WIDTH) v = __ldg(trow + gx);
        S[sk(p)] = v;
    }
    __syncwarp();

    // Phase 2 (per-warp): 97-tap conv, 16-slot register window, R=16
    int x0 = lane * HR;
    ull acc[HR];
#pragma unroll
    for (int r = 0; r < HR; r++) acc[r] = 0ull;

    ull win[16];
#pragma unroll
    for (int k = 0; k < 16; k++) win[k] = S[sk(x0 + k)];

#pragma unroll
    for (int J = 0; J < 96; J += 8) {
#pragma unroll
        for (int jj = 0; jj < 8; jj++) {
            const int j = J + jj;
            ull wj = sw[j];
#pragma unroll
            for (int r = 0; r < HR; r++)
                acc[r] = ffma2u(wj, win[(j + r) & 15], acc[r]);
            win[j & 15] = S[sk(x0 + j + 16)];   // loads inputs 16..111
        }
    }
    {
        ull w96 = sw[96];
#pragma unroll
        for (int r = 0; r < HR; r++)
            acc[r] = ffma2u(w96, win[(96 + r) & 15], acc[r]);
    }
    __syncwarp();   // all lanes done reading the segment

    // Phase 3 (per-warp): store blurred field at local output positions [0,512)
#pragma unroll
    for (int r = 0; r < HR; r++) S[sk(x0 + r)] = acc[r];
    __syncwarp();

    // Phase 4 (per-warp): bilinear sample, lane-consecutive x.
    // unroll 1: keeps the live temp set small (helps the reg cap); each
    // iteration still issues 16 independent gathers for MLP.
    const float gy = (float)y * (2.0f / (HEIGHT - 1)) - 1.0f;
    size_t rowoff = (size_t)y * WIDTH;

#pragma unroll 1
    for (int k = 0; k < HR; k++) {
        int lp = lane + k * 32;
        int x  = segx + lp;
        float dxf, dyf;
        unpackf2(S[sk(lp)], dxf, dyf);
        float gx = (float)x * (2.0f / (WIDTH - 1)) - 1.0f;
        // reference: x-coord gets blurred ch0 (dy), y-coord gets blurred ch1 (dx)
        float sx = fminf(fmaxf(gx + dxf, -1.0f), 1.0f);
        float sy = fminf(fmaxf(gy + dyf, -1.0f), 1.0f);
        float px = (sx + 1.0f) * 0.5f * (float)(WIDTH - 1);
        float py = (sy + 1.0f) * 0.5f * (float)(HEIGHT - 1);
        float fx = floorf(px), fy = floorf(py);
        float wx = px - fx,    wy = py - fy;
        int ix0 = (int)fx;
        int iy0 = (int)fy;
        int ix1 = min(ix0 + 1, WIDTH - 1);
        int iy1 = min(iy0 + 1, HEIGHT - 1);
        size_t o00 = (size_t)iy0 * WIDTH + ix0;
        size_t o01 = (size_t)iy0 * WIDTH + ix1;
        size_t o10 = (size_t)iy1 * WIDTH + ix0;
        size_t o11 = (size_t)iy1 * WIDTH + ix1;
#pragma unroll
        for (int c = 0; c < 4; c++) {
            const float* src = (c < 3) ? (img + (size_t)c * HW) : msk;
            float v00 = __ldg(src + o00);
            float v01 = __ldg(src + o01);
            float v10 = __ldg(src + o10);
            float v11 = __ldg(src + o11);
            float top = v00 * (1.0f - wx) + v01 * wx;
            float bot = v10 * (1.0f - wx) + v11 * wx;
            out[(size_t)c * HW + rowoff + x] = top * (1.0f - wy) + bot * wy;
        }
    }
}

// ---------------- launch ----------------
extern "C" void kernel_launch(void* const* d_in, const int* in_sizes, int n_in,
                              void* d_out, int out_size) {
    const float* image     = (const float*)d_in[0];  // (3, H, W)
    const float* mask      = (const float*)d_in[1];  // (1, H, W)
    const float* drand     = (const float*)d_in[2];  // (1, 2, H, W)
    const float* log_sigma = (const float*)d_in[3];  // (2,)
    const float* log_alpha = (const float*)d_in[4];  // (2,)
    float* out = (float*)d_out;                      // img(3HW) then mask(HW)

    vblur_kernel<<<dim3(WIDTH / 32, HEIGHT / VROWS), 256>>>(drand, log_sigma, log_alpha);
    hblur_sample_kernel<<<HEIGHT / 2, 256>>>(image, mask, out, log_sigma, log_alpha);
}